// round 5
// baseline (speedup 1.0000x reference)
#include <cuda_runtime.h>
#include <stdint.h>
#include <math.h>

// Problem constants
#define T_   4096
#define D_   128
#define H_   512
#define H3_  1536
#define WN_  4

#define GC   128      // CTAs in sequential kernel (all co-resident on 148 SMs)
#define NT   256      // threads per CTA

// ---------------- device scratch ----------------
__device__ float    g_XW [T_ * H3_];          //  25 MB : x@W + b
__device__ float    g_XWa[T_ * H_];           //   8 MB : x@Wa + ba
__device__ float    g_GWx[T_ * WN_ * H3_];    // 100 MB : emb[wid]@Ww + bw
__device__ float    g_cw [WN_ * H_];          // per-step c_w broadcast
__device__ unsigned g_meta[T_];               // nact(3b) + [w(2b)|d(5b)] x4
__device__ unsigned g_flag2[GC];              // contiguous barrier flags

// ---------------- acquire/release flag ops ----------------
__device__ __forceinline__ unsigned ld_acq(const unsigned* p) {
    unsigned v;
    asm volatile("ld.acquire.gpu.global.u32 %0, [%1];" : "=r"(v) : "l"(p) : "memory");
    return v;
}
__device__ __forceinline__ void st_rel(unsigned* p, unsigned v) {
    asm volatile("st.release.gpu.global.u32 [%0], %1;" :: "l"(p), "r"(v) : "memory");
}

// warp-0 poll: 128 contiguous flags, 4 per lane, coalesced
__device__ __forceinline__ void pollwait(unsigned s, int lane) {
    for (;;) {
        unsigned a = ld_acq(g_flag2 + lane);
        unsigned b = ld_acq(g_flag2 + lane + 32);
        unsigned d = ld_acq(g_flag2 + lane + 64);
        unsigned e = ld_acq(g_flag2 + lane + 96);
        bool ok = (a >= s) && (b >= s) && (d >= s) && (e >= s);
        if (__all_sync(0xFFFFFFFFu, ok)) break;
    }
}

// ---------------- fast transcendentals (validated: rel_err 3.5e-7) ----------------
__device__ __forceinline__ float fsig(float x) { return 1.0f / (1.0f + __expf(-x)); }
__device__ __forceinline__ float ftan(float x) {
    float ax = fabsf(x);
    float e  = __expf(-2.0f * ax);
    float t  = (1.0f - e) / (1.0f + e);
    return copysignf(t, x);
}

// ---------------- prep: flag reset + mask dtype detect + meta encode ----------------
__global__ void k_prep(const unsigned* __restrict__ mask32,
                       const void* __restrict__ mask,
                       const int*  __restrict__ wstarts)
{
    __shared__ int sflags;
    int tid = threadIdx.x;
    if (tid == 0) sflags = 7;
    if (tid < GC) g_flag2[tid] = 0;
    __syncthreads();
    int bad = 0;
    for (int i = tid; i < 4096; i += 1024) {
        unsigned w = mask32[i];
        if (w > 1u)                      bad |= 1;   // not int32 0/1
        if (w != 0u && w != 0x3F800000u) bad |= 2;   // not float32 0/1
        if (w & 0xFEFEFEFEu)             bad |= 4;   // not uint8 0/1
    }
    if (bad) atomicAnd(&sflags, ~bad);
    __syncthreads();
    int flags = sflags;
    int mode = (flags & 1) ? 0 : ((flags & 2) ? 1 : 2);
    for (int t = tid; t < T_; t += 1024) {
        unsigned m = 0;
        int nact = 0;
        #pragma unroll
        for (int w = 0; w < WN_; ++w) {
            int i = t * WN_ + w;
            int on = (mode == 0) ? (((const int*)mask)[i] != 0)
                   : (mode == 1) ? (((const float*)mask)[i] != 0.0f)
                                 : (((const unsigned char*)mask)[i] != 0);
            if (on) {
                int d = t - wstarts[i];
                if (d < 1) d = 1;
                if (d > 31) d = 31;
                m |= (unsigned)(w | (d << 2)) << (3 + 7 * nact);
                ++nact;
            }
        }
        g_meta[t] = m | (unsigned)nact;
    }
}

// ---------------- precompute GEMM ----------------
// sel==2 : C=g_GWx (gather-A), N=1536
// sel==3 : fused — bx<24: C=g_XW, else C=g_XWa
__global__ __launch_bounds__(256) void k_gemm(
    const float* __restrict__ A, const int* __restrict__ gidx,
    const float* __restrict__ Bm, const float* __restrict__ bias,
    const float* __restrict__ B2, const float* __restrict__ bias2,
    int M, int K, int sel)
{
    float* C; int N, bn;
    const float* B  = Bm;
    const float* bs = bias;
    if (sel == 2) { C = g_GWx; N = H3_; bn = blockIdx.x * 64; }
    else {
        if (blockIdx.x < 24) { C = g_XW;  N = H3_; bn = blockIdx.x * 64; }
        else { C = g_XWa; N = H_; bn = (blockIdx.x - 24) * 64; B = B2; bs = bias2; }
    }

    __shared__ float As[16 * 130];
    __shared__ float Bs[16 * 64];

    int tid = threadIdx.x;
    int bm = blockIdx.y * 128;
    int tx = tid & 15;
    int ty = tid >> 4;

    float acc[8][4];
    #pragma unroll
    for (int i = 0; i < 8; ++i)
        #pragma unroll
        for (int j = 0; j < 4; ++j) acc[i][j] = 0.0f;

    for (int k0 = 0; k0 < K; k0 += 16) {
        #pragma unroll
        for (int i = 0; i < 2; ++i) {
            int f = tid + i * 256;
            int row = f >> 2, kq = (f & 3) * 4;
            int ar = gidx ? gidx[bm + row] : (bm + row);
            float4 v = *(const float4*)(A + (size_t)ar * K + k0 + kq);
            As[(kq + 0) * 130 + row] = v.x;
            As[(kq + 1) * 130 + row] = v.y;
            As[(kq + 2) * 130 + row] = v.z;
            As[(kq + 3) * 130 + row] = v.w;
        }
        {
            int row = tid >> 4, cq = (tid & 15) * 4;
            float4 v = *(const float4*)(B + (size_t)(k0 + row) * N + bn + cq);
            *(float4*)&Bs[row * 64 + cq] = v;
        }
        __syncthreads();
        #pragma unroll
        for (int kk = 0; kk < 16; ++kk) {
            float a[8], b[4];
            #pragma unroll
            for (int i = 0; i < 8; ++i) a[i] = As[kk * 130 + ty + i * 16];
            #pragma unroll
            for (int j = 0; j < 4; ++j) b[j] = Bs[kk * 64 + tx + j * 16];
            #pragma unroll
            for (int i = 0; i < 8; ++i)
                #pragma unroll
                for (int j = 0; j < 4; ++j) acc[i][j] += a[i] * b[j];
        }
        __syncthreads();
    }
    #pragma unroll
    for (int i = 0; i < 8; ++i) {
        int m = bm + ty + i * 16;
        #pragma unroll
        for (int j = 0; j < 4; ++j) {
            int n = bn + tx + j * 16;
            C[(size_t)m * N + n] = acc[i][j] + bs[n];
        }
    }
}

// ---------------- smem layout (float offsets) ----------------
#define SM_U    0                  // 3*512 float4  U slices [gate][k]
#define SM_UW   6144               // 3*512 float4  Uw slices
#define SM_UA   12288              // 512 float4    Ua slice [k]
#define SM_HS   14336              // [2][4][128] float4 word h states
#define SM_CS   18432              // [2][4][128] float4 word c states
#define SM_HP   22528              // 512  h(t-1)
#define SM_CP   23040              // 512  c(t-1)
#define SM_RA   23552              // [2][12] float4 word-gate dots
#define SM_RB   23648              // 4 float4 main-gate dots (3 used)
#define SM_RAL  23664              // 4 float4 alpha dots
#define SM_BXW  23680              // [2][3+1] float4 XW biases
#define SM_BXA  23712              // [2] float4 XWa biases
#define SM_BGW  23720              // [2][12] float4 GWx biases
#define SM_CWO  23816              // 4 float4 own c_w columns
#define SM_META 23832              // 4096 uint
#define SM_TOTF (SM_META + 4096)
#define SMEM_BYTES (SM_TOTF * 4)

// warp task: 4-column dot, weights [k]->float4, state scalar per k (smem)
__device__ __forceinline__ float4 dotx4(const float4* __restrict__ w,
                                        const float*  __restrict__ h, int lane) {
    float ax = 0.f, ay = 0.f, az = 0.f, aw = 0.f;
    #pragma unroll
    for (int i = 0; i < 16; ++i) {
        int k = i * 32 + lane;
        float4 ww = w[k];
        float  hh = h[k];
        ax += ww.x * hh; ay += ww.y * hh; az += ww.z * hh; aw += ww.w * hh;
    }
    #pragma unroll
    for (int o = 16; o > 0; o >>= 1) {
        ax += __shfl_xor_sync(0xFFFFFFFFu, ax, o);
        ay += __shfl_xor_sync(0xFFFFFFFFu, ay, o);
        az += __shfl_xor_sync(0xFFFFFFFFu, az, o);
        aw += __shfl_xor_sync(0xFFFFFFFFu, aw, o);
    }
    return make_float4(ax, ay, az, aw);
}

// same, state streamed from global via L2 (.cg)
__device__ __forceinline__ float4 dotx4_g(const float4* __restrict__ w,
                                          const float*  __restrict__ gh, int lane) {
    float ax = 0.f, ay = 0.f, az = 0.f, aw = 0.f;
    #pragma unroll
    for (int i = 0; i < 16; ++i) {
        int k = i * 32 + lane;
        float4 ww = w[k];
        float  hh = __ldcg(gh + k);
        ax += ww.x * hh; ay += ww.y * hh; az += ww.z * hh; aw += ww.w * hh;
    }
    #pragma unroll
    for (int o = 16; o > 0; o >>= 1) {
        ax += __shfl_xor_sync(0xFFFFFFFFu, ax, o);
        ay += __shfl_xor_sync(0xFFFFFFFFu, ay, o);
        az += __shfl_xor_sync(0xFFFFFFFFu, az, o);
        aw += __shfl_xor_sync(0xFFFFFFFFu, aw, o);
    }
    return make_float4(ax, ay, az, aw);
}

__device__ __forceinline__ float4 f4add(float4 a, float4 b) {
    return make_float4(a.x + b.x, a.y + b.y, a.z + b.z, a.w + b.w);
}

__global__ __launch_bounds__(NT, 1) void k_seq(
    float* __restrict__ out,                 // [T, 1024] = hidden|cell
    const float* __restrict__ U,
    const float* __restrict__ Uw,
    const float* __restrict__ Ua,
    const float* __restrict__ h0,
    const float* __restrict__ c0)
{
    extern __shared__ float sm[];
    unsigned* s_meta = (unsigned*)(sm + SM_META);
    float4* U4  = (float4*)(sm + SM_U);
    float4* UW4 = (float4*)(sm + SM_UW);
    float4* UA4 = (float4*)(sm + SM_UA);
    float4* HS4 = (float4*)(sm + SM_HS);
    float4* CS4 = (float4*)(sm + SM_CS);
    float4* HP4 = (float4*)(sm + SM_HP);
    float4* CP4 = (float4*)(sm + SM_CP);
    float4* RA4 = (float4*)(sm + SM_RA);
    float4* RB4 = (float4*)(sm + SM_RB);
    float4* RAL4= (float4*)(sm + SM_RAL);
    float4* BXW4= (float4*)(sm + SM_BXW);
    float4* BXA4= (float4*)(sm + SM_BXA);
    float4* BGW4= (float4*)(sm + SM_BGW);
    float4* CWO4= (float4*)(sm + SM_CWO);

    const int c     = blockIdx.x;
    const int tid   = threadIdx.x;
    const int jbase = 4 * c;
    const int warp  = tid >> 5, lane = tid & 31;

    // ---- one-time: weight column slices + meta table ----
    for (int idx = tid; idx < 3 * 512; idx += NT) {
        int gate = idx >> 9, k = idx & 511;
        U4 [gate * 512 + k] = *(const float4*)(U  + (size_t)k * H3_ + gate * 512 + jbase);
        UW4[gate * 512 + k] = *(const float4*)(Uw + (size_t)k * H3_ + gate * 512 + jbase);
    }
    for (int k = tid; k < 512; k += NT)
        UA4[k] = *(const float4*)(Ua + (size_t)k * H_ + jbase);
    for (int i = tid; i < T_; i += NT) s_meta[i] = g_meta[i];
    __syncthreads();

    unsigned seq = 0;

    // prefetch step-tn inputs + shadow dots for its d>=2 words
    auto prefetch_and_shadow = [&](int tn) {
        if (tn >= T_) return;
        unsigned m = s_meta[tn];
        int na = (int)(m & 7u);
        int bn = tn & 1;
        if (tid < 3)
            BXW4[bn * 4 + tid] = __ldcg((const float4*)(
                g_XW + (size_t)tn * H3_ + tid * 512 + jbase));
        else if (tid == 3)
            BXA4[bn] = __ldcg((const float4*)(g_XWa + (size_t)tn * H_ + jbase));
        else if (tid >= 4 && tid < 4 + 3 * na) {
            int q = tid - 4, wi = q / 3, gate = q - wi * 3;
            int w = (int)((m >> (3 + 7 * wi)) & 3u);
            BGW4[bn * 12 + q] = __ldcg((const float4*)(
                g_GWx + ((size_t)tn * WN_ + w) * H3_ + gate * 512 + jbase));
        }
        for (int q = tid; q < na * 128; q += NT) {
            int wi = q >> 7, k = q & 127;
            int d = (int)((m >> (5 + 7 * wi)) & 31u);
            int row = tn - d;
            if (d >= 2 && row >= 0) {
                const float4* src = (const float4*)(out + (size_t)row * 1024);
                HS4[bn * 512 + q] = __ldcg(src + k);
                CS4[bn * 512 + q] = __ldcg(src + 128 + k);
            }
        }
        __syncthreads();
        for (int q = warp; q < 3 * na; q += 8) {
            int wi = q / 3, gate = q - wi * 3;
            int d = (int)((m >> (5 + 7 * wi)) & 31u);
            if (d >= 2) {
                float4 r = dotx4(UW4 + gate * 512,
                                 sm + SM_HS + (bn * 512 + wi * 128) * 4, lane);
                if (lane == 0) RA4[bn * 12 + q] = f4add(r, BGW4[bn * 12 + q]);
            }
        }
    };

    prefetch_and_shadow(0);
    __syncthreads();

    for (int t = 0; t < T_; ++t) {
        const unsigned meta = s_meta[t];
        const int nact = (int)(meta & 7u);
        const int buf  = t & 1;
        int dws[4];
        #pragma unroll
        for (int wi = 0; wi < 4; ++wi) dws[wi] = (int)((meta >> (5 + 7 * wi)) & 31u);
        bool any_d1 = false;
        for (int wi = 0; wi < nact; ++wi) any_d1 |= (dws[wi] == 1);

        // ---- stage row t-1 (h|c) via L2 ----
        if (t) {
            const float4* src = (const float4*)(out + (size_t)(t - 1) * 1024);
            if (tid < 128) HP4[tid] = __ldcg(src + tid);
            else           CP4[tid - 128] = __ldcg(src + tid);
        } else {
            if (tid < 128) HP4[tid] = ((const float4*)h0)[tid];
            else           CP4[tid - 128] = ((const float4*)c0)[tid - 128];
        }
        __syncthreads();                                       // (1)

        if (nact) {
            // ---- fresh dots only for d==1 words (h_s = h_prev) ----
            if (any_d1) {
                for (int q = warp; q < 3 * nact; q += 8) {
                    int wi = q / 3, gate = q - wi * 3;
                    if (dws[wi] == 1) {
                        float4 r = dotx4(UW4 + gate * 512, sm + SM_HP, lane);
                        if (lane == 0) RA4[buf * 12 + q] = f4add(r, BGW4[buf * 12 + q]);
                    }
                }
                __syncthreads();                               // (2)
            }
            // ---- warp0: c_w combine + publish + arrive A ----
            ++seq;
            if (warp == 0) {
                if (lane < nact) {
                    int wi = lane;
                    float4 f4v = RA4[buf * 12 + wi * 3 + 0];
                    float4 i4v = RA4[buf * 12 + wi * 3 + 1];
                    float4 g4v = RA4[buf * 12 + wi * 3 + 2];
                    float4 cs = (dws[wi] == 1) ? CP4[c]
                              : CS4[buf * 512 + wi * 128 + c];
                    float4 cw;
                    cw.x = fsig(f4v.x) * cs.x + fsig(i4v.x) * ftan(g4v.x);
                    cw.y = fsig(f4v.y) * cs.y + fsig(i4v.y) * ftan(g4v.y);
                    cw.z = fsig(f4v.z) * cs.z + fsig(i4v.z) * ftan(g4v.z);
                    cw.w = fsig(f4v.w) * cs.w + fsig(i4v.w) * ftan(g4v.w);
                    *(float4*)(g_cw + wi * H_ + jbase) = cw;
                    CWO4[wi] = cw;
                }
                __syncwarp();
                if (lane == 0) st_rel(&g_flag2[c], seq);
            }
            // ---- warps 5-7: main-gate dots (U . h_prev), overlap poll ----
            if (warp >= 5) {
                int gate = warp - 5;
                float4 r = dotx4(U4 + gate * 512, sm + SM_HP, lane);
                if (lane == 0) RB4[gate] = f4add(r, BXW4[buf * 4 + gate]);
            }
            // ---- warp 0: poll barrier A ----
            if (warp == 0) pollwait(seq, lane);
            __syncthreads();                                   // (3)

            // ---- alpha dots (Ua . c_w, c_w streamed from L2) ----
            if (warp < nact) {
                float4 r = dotx4_g(UA4, g_cw + warp * H_, lane);
                if (lane == 0) RAL4[warp] = f4add(r, BXA4[buf]);
            }
            __syncthreads();                                   // (4)
        } else {
            if (warp < 3) {
                float4 r = dotx4(U4 + warp * 512, sm + SM_HP, lane);
                if (lane == 0) RB4[warp] = f4add(r, BXW4[buf * 4 + warp]);
            }
            __syncthreads();                                   // (2')
        }

        // ---- tid0: final combine + out store + arrive B ----
        ++seq;
        if (tid == 0) {
            float4 gi = RB4[0], go = RB4[1], gg = RB4[2];
            float ig0 = fsig(gi.x), ig1 = fsig(gi.y), ig2 = fsig(gi.z), ig3 = fsig(gi.w);
            float og0 = fsig(go.x), og1 = fsig(go.y), og2 = fsig(go.z), og3 = fsig(go.w);
            float gt0 = ftan(gg.x), gt1 = ftan(gg.y), gt2 = ftan(gg.z), gt3 = ftan(gg.w);
            float c10, c11, c12, c13;
            if (nact) {
                float d0 = __expf(ig0), d1 = __expf(ig1),
                      d2 = __expf(ig2), d3 = __expf(ig3);
                float n0 = d0 * gt0, n1 = d1 * gt1, n2 = d2 * gt2, n3 = d3 * gt3;
                for (int wi = 0; wi < nact; ++wi) {
                    float4 al = RAL4[wi];
                    float4 cw = CWO4[wi];
                    float e0 = __expf(fsig(al.x)), e1 = __expf(fsig(al.y));
                    float e2 = __expf(fsig(al.z)), e3 = __expf(fsig(al.w));
                    d0 += e0; d1 += e1; d2 += e2; d3 += e3;
                    n0 += e0 * cw.x; n1 += e1 * cw.y; n2 += e2 * cw.z; n3 += e3 * cw.w;
                }
                c10 = n0 / d0; c11 = n1 / d1; c12 = n2 / d2; c13 = n3 / d3;
            } else {
                float4 cp = CP4[c];
                c10 = (1.0f - ig0) * cp.x + ig0 * gt0;
                c11 = (1.0f - ig1) * cp.y + ig1 * gt1;
                c12 = (1.0f - ig2) * cp.z + ig2 * gt2;
                c13 = (1.0f - ig3) * cp.w + ig3 * gt3;
            }
            float4 h1 = make_float4(og0 * ftan(c10), og1 * ftan(c11),
                                    og2 * ftan(c12), og3 * ftan(c13));
            float4* orow = (float4*)(out + (size_t)t * 1024);
            orow[c]       = h1;
            orow[128 + c] = make_float4(c10, c11, c12, c13);
            st_rel(&g_flag2[c], seq);
        }
        // ---- barrier-B shadow: prefetch + d>=2 word dots for t+1 ----
        prefetch_and_shadow(t + 1);
        // ---- warp 0: poll barrier B ----
        if (warp == 0) pollwait(seq, lane);
        __syncthreads();                                       // (6)
    }
}

// ---------------- launch (4 kernels) ----------------
extern "C" void kernel_launch(void* const* d_in, const int* in_sizes, int n_in,
                              void* d_out, int out_size) {
    const float* x        = (const float*)d_in[0];
    const int*   word_ids = (const int*)  d_in[1];
    const int*   wstarts  = (const int*)  d_in[2];
    const void*  wmask    = (const void*) d_in[3];
    const float* h0       = (const float*)d_in[4];
    const float* c0       = (const float*)d_in[5];
    const float* emb      = (const float*)d_in[6];
    const float* W        = (const float*)d_in[7];
    const float* U        = (const float*)d_in[8];
    const float* b        = (const float*)d_in[9];
    const float* Wa       = (const float*)d_in[10];
    const float* Ua       = (const float*)d_in[11];
    const float* ba       = (const float*)d_in[12];
    const float* Ww       = (const float*)d_in[13];
    const float* Uw       = (const float*)d_in[14];
    const float* bw       = (const float*)d_in[15];
    float* out = (float*)d_out;

    k_prep<<<1, 1024>>>((const unsigned*)wmask, wmask, wstarts);

    dim3 gx(32, T_ / 128);
    k_gemm<<<gx, 256>>>(x, nullptr, W, b, Wa, ba, T_, D_, 3);
    dim3 gw(H3_ / 64, (T_ * WN_) / 128);
    k_gemm<<<gw, 256>>>(emb, word_ids, Ww, bw, nullptr, nullptr, T_ * WN_, 256, 2);

    static_assert(SMEM_BYTES < 220 * 1024, "smem");
    cudaFuncSetAttribute(k_seq, cudaFuncAttributeMaxDynamicSharedMemorySize,
                         SMEM_BYTES);
    k_seq<<<GC, NT, SMEM_BYTES>>>(out, U, Uw, Ua, h0, c0);
}

// round 6
// speedup vs baseline: 1.5942x; 1.5942x over previous
#include <cuda_runtime.h>
#include <stdint.h>
#include <math.h>

// Problem constants
#define T_   4096
#define D_   128
#define H_   512
#define H3_  1536
#define WN_  4

#define GC   128      // CTAs in sequential kernel (all co-resident)
#define NT   256      // threads per CTA

// ---------------- device scratch ----------------
__device__ float    g_XW [T_ * H3_];          //  25 MB : x@W + b
__device__ float    g_XWa[T_ * H_];           //   8 MB : x@Wa + ba
__device__ float    g_GWx[T_ * WN_ * H3_];    // 100 MB : emb[wid]@Ww + bw
__device__ float    g_cwt[(size_t)T_ * 2048]; //  32 MB : per-step c_w (write-once)
__device__ unsigned g_meta[T_];               // nact(3b) + [w(2b)|d(5b)] x4
__device__ unsigned g_flag[GC * 32];          // spread barrier flags (128B apart)

// ---------------- acquire/release flag ops ----------------
__device__ __forceinline__ unsigned ld_acq(const unsigned* p) {
    unsigned v;
    asm volatile("ld.acquire.gpu.global.u32 %0, [%1];" : "=r"(v) : "l"(p) : "memory");
    return v;
}
__device__ __forceinline__ void st_rel(unsigned* p, unsigned v) {
    asm volatile("st.release.gpu.global.u32 [%0], %1;" :: "l"(p), "r"(v) : "memory");
}

// ---------------- fast transcendentals (validated rel_err 3.5e-7) ----------------
__device__ __forceinline__ float fsig(float x) { return 1.0f / (1.0f + __expf(-x)); }
__device__ __forceinline__ float ftan(float x) {
    float ax = fabsf(x);
    float e  = __expf(-2.0f * ax);
    float t  = (1.0f - e) / (1.0f + e);
    return copysignf(t, x);
}

// ---------------- prep: flag reset + mask dtype detect + meta encode ----------------
__global__ void k_prep(const unsigned* __restrict__ mask32,
                       const void* __restrict__ mask,
                       const int*  __restrict__ wstarts)
{
    __shared__ int sflags;
    int tid = threadIdx.x;
    if (tid == 0) sflags = 7;
    for (int i = tid; i < GC * 32; i += 1024) g_flag[i] = 0;
    __syncthreads();
    int bad = 0;
    for (int i = tid; i < 4096; i += 1024) {
        unsigned w = mask32[i];
        if (w > 1u)                      bad |= 1;   // not int32 0/1
        if (w != 0u && w != 0x3F800000u) bad |= 2;   // not float32 0/1
        if (w & 0xFEFEFEFEu)             bad |= 4;   // not uint8 0/1
    }
    if (bad) atomicAnd(&sflags, ~bad);
    __syncthreads();
    int flags = sflags;
    int mode = (flags & 1) ? 0 : ((flags & 2) ? 1 : 2);
    for (int t = tid; t < T_; t += 1024) {
        unsigned m = 0;
        int nact = 0;
        #pragma unroll
        for (int w = 0; w < WN_; ++w) {
            int i = t * WN_ + w;
            int on = (mode == 0) ? (((const int*)mask)[i] != 0)
                   : (mode == 1) ? (((const float*)mask)[i] != 0.0f)
                                 : (((const unsigned char*)mask)[i] != 0);
            if (on) {
                int d = t - wstarts[i];
                if (d < 1) d = 1;
                if (d > 31) d = 31;
                m |= (unsigned)(w | (d << 2)) << (3 + 7 * nact);
                ++nact;
            }
        }
        g_meta[t] = m | (unsigned)nact;
    }
}

// ---------------- precompute GEMM ----------------
// sel==2 : C=g_GWx (gather-A), N=1536 ; sel==3 : fused XW / XWa
__global__ __launch_bounds__(256) void k_gemm(
    const float* __restrict__ A, const int* __restrict__ gidx,
    const float* __restrict__ Bm, const float* __restrict__ bias,
    const float* __restrict__ B2, const float* __restrict__ bias2,
    int M, int K, int sel)
{
    float* C; int N, bn;
    const float* B  = Bm;
    const float* bs = bias;
    if (sel == 2) { C = g_GWx; N = H3_; bn = blockIdx.x * 64; }
    else {
        if (blockIdx.x < 24) { C = g_XW;  N = H3_; bn = blockIdx.x * 64; }
        else { C = g_XWa; N = H_; bn = (blockIdx.x - 24) * 64; B = B2; bs = bias2; }
    }

    __shared__ float As[16 * 130];
    __shared__ float Bs[16 * 64];

    int tid = threadIdx.x;
    int bm = blockIdx.y * 128;
    int tx = tid & 15;
    int ty = tid >> 4;

    float acc[8][4];
    #pragma unroll
    for (int i = 0; i < 8; ++i)
        #pragma unroll
        for (int j = 0; j < 4; ++j) acc[i][j] = 0.0f;

    for (int k0 = 0; k0 < K; k0 += 16) {
        #pragma unroll
        for (int i = 0; i < 2; ++i) {
            int f = tid + i * 256;
            int row = f >> 2, kq = (f & 3) * 4;
            int ar = gidx ? gidx[bm + row] : (bm + row);
            float4 v = *(const float4*)(A + (size_t)ar * K + k0 + kq);
            As[(kq + 0) * 130 + row] = v.x;
            As[(kq + 1) * 130 + row] = v.y;
            As[(kq + 2) * 130 + row] = v.z;
            As[(kq + 3) * 130 + row] = v.w;
        }
        {
            int row = tid >> 4, cq = (tid & 15) * 4;
            float4 v = *(const float4*)(B + (size_t)(k0 + row) * N + bn + cq);
            *(float4*)&Bs[row * 64 + cq] = v;
        }
        __syncthreads();
        #pragma unroll
        for (int kk = 0; kk < 16; ++kk) {
            float a[8], b[4];
            #pragma unroll
            for (int i = 0; i < 8; ++i) a[i] = As[kk * 130 + ty + i * 16];
            #pragma unroll
            for (int j = 0; j < 4; ++j) b[j] = Bs[kk * 64 + tx + j * 16];
            #pragma unroll
            for (int i = 0; i < 8; ++i)
                #pragma unroll
                for (int j = 0; j < 4; ++j) acc[i][j] += a[i] * b[j];
        }
        __syncthreads();
    }
    #pragma unroll
    for (int i = 0; i < 8; ++i) {
        int m = bm + ty + i * 16;
        #pragma unroll
        for (int j = 0; j < 4; ++j) {
            int n = bn + tx + j * 16;
            C[(size_t)m * N + n] = acc[i][j] + bs[n];
        }
    }
}

// ---------------- smem layout (float offsets) ----------------
#define SM_U     0                   // 3*512 float4  U slices [gate][k]
#define SM_UW    6144                // 3*512 float4  Uw slices
#define SM_UA    12288               // 512 float4    Ua slice [k]
#define SM_RB    14336               // 4 float4      gate dots (3 used)
#define SM_RAL   14352               // 4 float4      alpha dots
#define SM_RASH  14368               // 12 float4     word-gate dot results
#define SM_CWO   14416               // [2][4] float4 own c_w columns (parity)
#define SM_CPRV  14448               // 1 float4      c_prev own columns
#define SM_CSSH  14452               // 4 float4      shadow c_s own columns
#define SM_META  14472               // 4096 uint
#define SM_TOTF  (SM_META + 4096)
#define SMEM_BYTES (SM_TOTF * 4)

// warp dot: weights float4[512] in smem, state float[512] in GLOBAL,
// bias float4 in global (lane0 preloads); result (+bias) returned on lane0.
__device__ __forceinline__ float4 dotg(const float4* __restrict__ w,
                                       const float*  __restrict__ gh,
                                       const float*  __restrict__ gb,
                                       int lane) {
    float4 b = make_float4(0.f, 0.f, 0.f, 0.f);
    if (lane == 0) b = *(const float4*)gb;
    float ax = 0.f, ay = 0.f, az = 0.f, aw = 0.f;
    #pragma unroll
    for (int i = 0; i < 16; ++i) {
        int k = i * 32 + lane;
        float  hh = gh[k];
        float4 ww = w[k];
        ax += ww.x * hh; ay += ww.y * hh; az += ww.z * hh; aw += ww.w * hh;
    }
    #pragma unroll
    for (int o = 16; o > 0; o >>= 1) {
        ax += __shfl_xor_sync(0xFFFFFFFFu, ax, o);
        ay += __shfl_xor_sync(0xFFFFFFFFu, ay, o);
        az += __shfl_xor_sync(0xFFFFFFFFu, az, o);
        aw += __shfl_xor_sync(0xFFFFFFFFu, aw, o);
    }
    return make_float4(ax + b.x, ay + b.y, az + b.z, aw + b.w);
}

__global__ __launch_bounds__(NT, 1) void k_seq(
    float* __restrict__ out,                 // [T, 1024] = hidden|cell
    const float* __restrict__ U,
    const float* __restrict__ Uw,
    const float* __restrict__ Ua,
    const float* __restrict__ h0,
    const float* __restrict__ c0)
{
    extern __shared__ float sm[];
    unsigned* s_meta = (unsigned*)(sm + SM_META);
    float4* U4   = (float4*)(sm + SM_U);
    float4* UW4  = (float4*)(sm + SM_UW);
    float4* UA4  = (float4*)(sm + SM_UA);
    float4* RB4  = (float4*)(sm + SM_RB);
    float4* RAL4 = (float4*)(sm + SM_RAL);
    float4* RASH4= (float4*)(sm + SM_RASH);
    float4* CWO4 = (float4*)(sm + SM_CWO);
    float4* CPRV4= (float4*)(sm + SM_CPRV);
    float4* CSSH4= (float4*)(sm + SM_CSSH);

    const int c     = blockIdx.x;
    const int tid   = threadIdx.x;
    const int jbase = 4 * c;
    const int warp  = tid >> 5, lane = tid & 31;

    // ---- one-time: weight column slices + meta table ----
    for (int idx = tid; idx < 3 * 512; idx += NT) {
        int gate = idx >> 9, k = idx & 511;
        U4 [gate * 512 + k] = *(const float4*)(U  + (size_t)k * H3_ + gate * 512 + jbase);
        UW4[gate * 512 + k] = *(const float4*)(Uw + (size_t)k * H3_ + gate * 512 + jbase);
    }
    for (int k = tid; k < 512; k += NT)
        UA4[k] = *(const float4*)(Ua + (size_t)k * H_ + jbase);
    for (int i = tid; i < T_; i += NT) s_meta[i] = g_meta[i];
    __syncthreads();

    unsigned seq = 0;
    unsigned* myflag = &g_flag[c * 32];

    for (int t = 0; t < T_; ++t) {
        const unsigned meta = s_meta[t];
        const int nact = (int)(meta & 7u);
        const unsigned mN = (t + 1 < T_) ? s_meta[t + 1] : 0u;
        const int nactN = (int)(mN & 7u);

        int wT[4], dT[4], wN[4], dN[4];
        #pragma unroll
        for (int i = 0; i < 4; ++i) {
            unsigned f = meta >> (3 + 7 * i);
            wT[i] = (int)(f & 3u); dT[i] = (int)((f >> 2) & 31u);
            unsigned g = mN >> (3 + 7 * i);
            wN[i] = (int)(g & 3u); dN[i] = (int)((g >> 2) & 31u);
        }
        bool lateT = false;
        for (int i = 0; i < nact; ++i) lateT |= (dT[i] == 1);

        const float* rowHprev = t ? (out + (size_t)(t - 1) * 1024) : h0;
        const float* rowCprev = t ? (out + (size_t)(t - 1) * 1024 + 512) : c0;

        // ======== late phase: d==1 word gates (needs h_{t-1}) ========
        if (lateT) {
            if (tid == 0) CPRV4[0] = *(const float4*)(rowCprev + jbase);
            for (int d = warp; d < 3 * nact; d += 8) {
                int wi = d / 3, gate = d - wi * 3;
                if (dT[wi] == 1) {
                    float4 r = dotg(UW4 + gate * 512, rowHprev,
                                    g_GWx + ((size_t)t * WN_ + wT[wi]) * H3_
                                          + gate * 512 + jbase, lane);
                    if (lane == 0) RASH4[d] = r;
                }
            }
            __syncthreads();
            ++seq;
            if (warp == 0) {
                if (lane < nact && dT[lane] == 1) {
                    float4 f4v = RASH4[lane * 3 + 0];
                    float4 i4v = RASH4[lane * 3 + 1];
                    float4 g4v = RASH4[lane * 3 + 2];
                    float4 cs  = CPRV4[0];
                    float4 cw;
                    cw.x = fsig(f4v.x) * cs.x + fsig(i4v.x) * ftan(g4v.x);
                    cw.y = fsig(f4v.y) * cs.y + fsig(i4v.y) * ftan(g4v.y);
                    cw.z = fsig(f4v.z) * cs.z + fsig(i4v.z) * ftan(g4v.z);
                    cw.w = fsig(f4v.w) * cs.w + fsig(i4v.w) * ftan(g4v.w);
                    *(float4*)(g_cwt + (size_t)t * 2048 + lane * 512 + jbase) = cw;
                    CWO4[(t & 1) * 4 + lane] = cw;
                }
                __syncwarp();
                if (lane == 0) st_rel(myflag, seq);
            }
            if (tid < GC) { while (ld_acq(&g_flag[tid * 32]) < seq) {} }
            __syncthreads();
        }

        // ======== main phase: flat task loop ========
        // [0,3): gate dots  [3,3+nact): alpha dots
        // [base_sh, base_mi): shadow word dots for t+1 (d>=2)
        // [base_mi]: c_prev micro-load  (base_mi, base_mi+nactN]: c_s micro-loads
        const int base_sh = 3 + nact;
        const int base_mi = base_sh + 3 * nactN;
        const int ntasks  = base_mi + 1 + nactN;
        for (int d = warp; d < ntasks; d += 8) {
            if (d < 3) {
                float4 r = dotg(U4 + d * 512, rowHprev,
                                g_XW + (size_t)t * H3_ + d * 512 + jbase, lane);
                if (lane == 0) RB4[d] = r;
            } else if (d < base_sh) {
                int wi = d - 3;
                float4 r = dotg(UA4, g_cwt + (size_t)t * 2048 + wi * 512,
                                g_XWa + (size_t)t * H_ + jbase, lane);
                if (lane == 0) RAL4[wi] = r;
            } else if (d < base_mi) {
                int q = d - base_sh, wi = q / 3, gate = q - wi * 3;
                if (dN[wi] >= 2) {
                    const float* row = out + (size_t)(t + 1 - dN[wi]) * 1024;
                    float4 r = dotg(UW4 + gate * 512, row,
                                    g_GWx + ((size_t)(t + 1) * WN_ + wN[wi]) * H3_
                                          + gate * 512 + jbase, lane);
                    if (lane == 0) RASH4[q] = r;
                }
            } else if (d == base_mi) {
                if (lane == 0) CPRV4[0] = *(const float4*)(rowCprev + jbase);
            } else {
                int wi = d - base_mi - 1;
                if (dN[wi] >= 2 && lane == 0)
                    CSSH4[wi] = *(const float4*)(out +
                        (size_t)(t + 1 - dN[wi]) * 1024 + 512 + jbase);
            }
        }
        __syncthreads();

        // ======== combine + publish (warp 0 only) ========
        ++seq;
        if (warp == 0) {
            // shadow c_w(t+1) for d>=2 words
            if (lane < nactN && dN[lane] >= 2) {
                float4 f4v = RASH4[lane * 3 + 0];
                float4 i4v = RASH4[lane * 3 + 1];
                float4 g4v = RASH4[lane * 3 + 2];
                float4 cs  = CSSH4[lane];
                float4 cw;
                cw.x = fsig(f4v.x) * cs.x + fsig(i4v.x) * ftan(g4v.x);
                cw.y = fsig(f4v.y) * cs.y + fsig(i4v.y) * ftan(g4v.y);
                cw.z = fsig(f4v.z) * cs.z + fsig(i4v.z) * ftan(g4v.z);
                cw.w = fsig(f4v.w) * cs.w + fsig(i4v.w) * ftan(g4v.w);
                *(float4*)(g_cwt + (size_t)(t + 1) * 2048 + lane * 512 + jbase) = cw;
                CWO4[((t + 1) & 1) * 4 + lane] = cw;
            }
            // final combine on lane 16
            if (lane == 16) {
                float4 gi = RB4[0], go = RB4[1], gg = RB4[2];
                float ig0 = fsig(gi.x), ig1 = fsig(gi.y), ig2 = fsig(gi.z), ig3 = fsig(gi.w);
                float og0 = fsig(go.x), og1 = fsig(go.y), og2 = fsig(go.z), og3 = fsig(go.w);
                float gt0 = ftan(gg.x), gt1 = ftan(gg.y), gt2 = ftan(gg.z), gt3 = ftan(gg.w);
                float c10, c11, c12, c13;
                if (nact) {
                    float d0 = __expf(ig0), d1 = __expf(ig1),
                          d2 = __expf(ig2), d3 = __expf(ig3);
                    float n0 = d0 * gt0, n1 = d1 * gt1, n2 = d2 * gt2, n3 = d3 * gt3;
                    for (int wi = 0; wi < nact; ++wi) {
                        float4 al = RAL4[wi];
                        float4 cw = CWO4[(t & 1) * 4 + wi];
                        float e0 = __expf(fsig(al.x)), e1 = __expf(fsig(al.y));
                        float e2 = __expf(fsig(al.z)), e3 = __expf(fsig(al.w));
                        d0 += e0; d1 += e1; d2 += e2; d3 += e3;
                        n0 += e0 * cw.x; n1 += e1 * cw.y;
                        n2 += e2 * cw.z; n3 += e3 * cw.w;
                    }
                    c10 = n0 / d0; c11 = n1 / d1; c12 = n2 / d2; c13 = n3 / d3;
                } else {
                    float4 cp = CPRV4[0];
                    c10 = (1.0f - ig0) * cp.x + ig0 * gt0;
                    c11 = (1.0f - ig1) * cp.y + ig1 * gt1;
                    c12 = (1.0f - ig2) * cp.z + ig2 * gt2;
                    c13 = (1.0f - ig3) * cp.w + ig3 * gt3;
                }
                float4 h1 = make_float4(og0 * ftan(c10), og1 * ftan(c11),
                                        og2 * ftan(c12), og3 * ftan(c13));
                float4* orow = (float4*)(out + (size_t)t * 1024);
                orow[c]       = h1;
                orow[128 + c] = make_float4(c10, c11, c12, c13);
            }
            __syncwarp();
            if (lane == 0) st_rel(myflag, seq);
        }
        // ======== barrier ========
        if (tid < GC) { while (ld_acq(&g_flag[tid * 32]) < seq) {} }
        __syncthreads();
    }
}

// ---------------- launch (4 kernels) ----------------
extern "C" void kernel_launch(void* const* d_in, const int* in_sizes, int n_in,
                              void* d_out, int out_size) {
    const float* x        = (const float*)d_in[0];
    const int*   word_ids = (const int*)  d_in[1];
    const int*   wstarts  = (const int*)  d_in[2];
    const void*  wmask    = (const void*) d_in[3];
    const float* h0       = (const float*)d_in[4];
    const float* c0       = (const float*)d_in[5];
    const float* emb      = (const float*)d_in[6];
    const float* W        = (const float*)d_in[7];
    const float* U        = (const float*)d_in[8];
    const float* b        = (const float*)d_in[9];
    const float* Wa       = (const float*)d_in[10];
    const float* Ua       = (const float*)d_in[11];
    const float* ba       = (const float*)d_in[12];
    const float* Ww       = (const float*)d_in[13];
    const float* Uw       = (const float*)d_in[14];
    const float* bw       = (const float*)d_in[15];
    float* out = (float*)d_out;

    k_prep<<<1, 1024>>>((const unsigned*)wmask, wmask, wstarts);

    dim3 gx(32, T_ / 128);
    k_gemm<<<gx, 256>>>(x, nullptr, W, b, Wa, ba, T_, D_, 3);
    dim3 gw(H3_ / 64, (T_ * WN_) / 128);
    k_gemm<<<gw, 256>>>(emb, word_ids, Ww, bw, nullptr, nullptr, T_ * WN_, 256, 2);

    static_assert(SMEM_BYTES < 220 * 1024, "smem");
    cudaFuncSetAttribute(k_seq, cudaFuncAttributeMaxDynamicSharedMemorySize,
                         SMEM_BYTES);
    k_seq<<<GC, NT, SMEM_BYTES>>>(out, U, Uw, Ua, h0, c0);
}

// round 9
// speedup vs baseline: 2.0081x; 1.2596x over previous
#include <cuda_runtime.h>
#include <stdint.h>
#include <math.h>

// Problem constants
#define T_   4096
#define D_   128
#define H_   512
#define H3_  1536
#define WN_  4

#define GC   128      // CTAs in sequential kernel (all co-resident)
#define NT   256      // threads per CTA

// ---------------- device scratch ----------------
__device__ float    g_XW [T_ * H3_];          //  25 MB : x@W + b
__device__ float    g_XWa[T_ * H_];           //   8 MB : x@Wa + ba
__device__ float    g_GWx[T_ * WN_ * H3_];    // 100 MB : emb[wid]@Ww + bw
__device__ float    g_cwt[(size_t)T_ * 2048]; //  32 MB : per-step c_w (write-once)
__device__ unsigned g_meta[T_];               // nact(3b) + [w(2b)|d(5b)] x4
__device__ unsigned g_flag[GC * 32];          // spread barrier flags (128B apart)

// ---------------- acquire/release flag ops ----------------
__device__ __forceinline__ unsigned ld_acq(const unsigned* p) {
    unsigned v;
    asm volatile("ld.acquire.gpu.global.u32 %0, [%1];" : "=r"(v) : "l"(p) : "memory");
    return v;
}
__device__ __forceinline__ void st_rel(unsigned* p, unsigned v) {
    asm volatile("st.release.gpu.global.u32 [%0], %1;" :: "l"(p), "r"(v) : "memory");
}

// ---------------- fast transcendentals (validated rel_err 3.5e-7) ----------------
__device__ __forceinline__ float fsig(float x) { return 1.0f / (1.0f + __expf(-x)); }
__device__ __forceinline__ float ftan(float x) {
    float ax = fabsf(x);
    float e  = __expf(-2.0f * ax);
    float t  = (1.0f - e) / (1.0f + e);
    return copysignf(t, x);
}

// ---------------- prep: flag reset + mask dtype detect + meta encode ----------------
__global__ void k_prep(const unsigned* __restrict__ mask32,
                       const void* __restrict__ mask,
                       const int*  __restrict__ wstarts)
{
    __shared__ int sflags;
    int tid = threadIdx.x;
    if (tid == 0) sflags = 7;
    for (int i = tid; i < GC * 32; i += 1024) g_flag[i] = 0;
    __syncthreads();
    int bad = 0;
    for (int i = tid; i < 4096; i += 1024) {
        unsigned w = mask32[i];
        if (w > 1u)                      bad |= 1;   // not int32 0/1
        if (w != 0u && w != 0x3F800000u) bad |= 2;   // not float32 0/1
        if (w & 0xFEFEFEFEu)             bad |= 4;   // not uint8 0/1
    }
    if (bad) atomicAnd(&sflags, ~bad);
    __syncthreads();
    int flags = sflags;
    int mode = (flags & 1) ? 0 : ((flags & 2) ? 1 : 2);
    for (int t = tid; t < T_; t += 1024) {
        unsigned m = 0;
        int nact = 0;
        #pragma unroll
        for (int w = 0; w < WN_; ++w) {
            int i = t * WN_ + w;
            int on = (mode == 0) ? (((const int*)mask)[i] != 0)
                   : (mode == 1) ? (((const float*)mask)[i] != 0.0f)
                                 : (((const unsigned char*)mask)[i] != 0);
            if (on) {
                int d = t - wstarts[i];
                if (d < 1) d = 1;
                if (d > 31) d = 31;
                m |= (unsigned)(w | (d << 2)) << (3 + 7 * nact);
                ++nact;
            }
        }
        g_meta[t] = m | (unsigned)nact;
    }
}

// ---------------- precompute GEMM ----------------
__global__ __launch_bounds__(256) void k_gemm(
    const float* __restrict__ A, const int* __restrict__ gidx,
    const float* __restrict__ Bm, const float* __restrict__ bias,
    const float* __restrict__ B2, const float* __restrict__ bias2,
    int M, int K, int sel)
{
    float* C; int N, bn;
    const float* B  = Bm;
    const float* bs = bias;
    if (sel == 2) { C = g_GWx; N = H3_; bn = blockIdx.x * 64; }
    else {
        if (blockIdx.x < 24) { C = g_XW;  N = H3_; bn = blockIdx.x * 64; }
        else { C = g_XWa; N = H_; bn = (blockIdx.x - 24) * 64; B = B2; bs = bias2; }
    }

    __shared__ float As[16 * 130];
    __shared__ float Bs[16 * 64];

    int tid = threadIdx.x;
    int bm = blockIdx.y * 128;
    int tx = tid & 15;
    int ty = tid >> 4;

    float acc[8][4];
    #pragma unroll
    for (int i = 0; i < 8; ++i)
        #pragma unroll
        for (int j = 0; j < 4; ++j) acc[i][j] = 0.0f;

    for (int k0 = 0; k0 < K; k0 += 16) {
        #pragma unroll
        for (int i = 0; i < 2; ++i) {
            int f = tid + i * 256;
            int row = f >> 2, kq = (f & 3) * 4;
            int ar = gidx ? gidx[bm + row] : (bm + row);
            float4 v = *(const float4*)(A + (size_t)ar * K + k0 + kq);
            As[(kq + 0) * 130 + row] = v.x;
            As[(kq + 1) * 130 + row] = v.y;
            As[(kq + 2) * 130 + row] = v.z;
            As[(kq + 3) * 130 + row] = v.w;
        }
        {
            int row = tid >> 4, cq = (tid & 15) * 4;
            float4 v = *(const float4*)(B + (size_t)(k0 + row) * N + bn + cq);
            *(float4*)&Bs[row * 64 + cq] = v;
        }
        __syncthreads();
        #pragma unroll
        for (int kk = 0; kk < 16; ++kk) {
            float a[8], b[4];
            #pragma unroll
            for (int i = 0; i < 8; ++i) a[i] = As[kk * 130 + ty + i * 16];
            #pragma unroll
            for (int j = 0; j < 4; ++j) b[j] = Bs[kk * 64 + tx + j * 16];
            #pragma unroll
            for (int i = 0; i < 8; ++i)
                #pragma unroll
                for (int j = 0; j < 4; ++j) acc[i][j] += a[i] * b[j];
        }
        __syncthreads();
    }
    #pragma unroll
    for (int i = 0; i < 8; ++i) {
        int m = bm + ty + i * 16;
        #pragma unroll
        for (int j = 0; j < 4; ++j) {
            int n = bn + tx + j * 16;
            C[(size_t)m * N + n] = acc[i][j] + bs[n];
        }
    }
}

// ---------------- smem layout (float offsets) ----------------
#define SM_U     0                   // 3*512 float4  U slices [gate][k]
#define SM_UW    6144                // 3*512 float4  Uw slices
#define SM_UA    12288               // 512 float4    Ua slice [k]
#define SM_RB    14336               // 3 float4      gate dots
#define SM_RAL   14352               // 4 float4      alpha dots
#define SM_RASH  14368               // 12 float4     word-gate dot results
#define SM_CWO   14416               // [2][4] float4 own c_w cols (parity)
#define SM_CPRV  14448               // 1 float4      c_prev own cols
#define SM_CSSH  14452               // 4 float4      shadow c_s own cols
#define SM_META  14472               // 4096 uint
#define SM_TOTF  (SM_META + 4096)
#define SMEM_BYTES (SM_TOTF * 4)

// warp dot (4 cols): weights float4[512] smem, state float[512] global,
// bias float4 global (lane0 preloads); result(+bias) valid on lane0.
__device__ __forceinline__ float4 dotg(const float4* __restrict__ w,
                                       const float*  __restrict__ gh,
                                       const float*  __restrict__ gb,
                                       int lane) {
    float4 b = make_float4(0.f, 0.f, 0.f, 0.f);
    if (lane == 0) b = *(const float4*)gb;
    float ax = 0.f, ay = 0.f, az = 0.f, aw = 0.f;
    #pragma unroll
    for (int i = 0; i < 16; ++i) {
        int k = i * 32 + lane;
        float  hh = gh[k];
        float4 ww = w[k];
        ax += ww.x * hh; ay += ww.y * hh; az += ww.z * hh; aw += ww.w * hh;
    }
    #pragma unroll
    for (int o = 16; o > 0; o >>= 1) {
        ax += __shfl_xor_sync(0xFFFFFFFFu, ax, o);
        ay += __shfl_xor_sync(0xFFFFFFFFu, ay, o);
        az += __shfl_xor_sync(0xFFFFFFFFu, az, o);
        aw += __shfl_xor_sync(0xFFFFFFFFu, aw, o);
    }
    return make_float4(ax + b.x, ay + b.y, az + b.z, aw + b.w);
}

// fused 12-col word dot: all three gates (f,i,g) of one word share the row
// load stream. Results(+bias) valid on lane0 in a[12].
__device__ __forceinline__ void dot12(const float4* __restrict__ UWbase,
                                      const float*  __restrict__ gh,
                                      const float*  __restrict__ gb,
                                      int lane, float* __restrict__ a) {
    float4 b0 = make_float4(0,0,0,0), b1 = b0, b2 = b0;
    if (lane == 0) {
        b0 = *(const float4*)(gb);
        b1 = *(const float4*)(gb + 512);
        b2 = *(const float4*)(gb + 1024);
    }
    #pragma unroll
    for (int i = 0; i < 12; ++i) a[i] = 0.f;
    #pragma unroll
    for (int i = 0; i < 16; ++i) {
        int k = i * 32 + lane;
        float  hh = gh[k];
        float4 x = UWbase[k];
        float4 y = UWbase[512 + k];
        float4 z = UWbase[1024 + k];
        a[0] += x.x * hh; a[1] += x.y * hh; a[2]  += x.z * hh; a[3]  += x.w * hh;
        a[4] += y.x * hh; a[5] += y.y * hh; a[6]  += y.z * hh; a[7]  += y.w * hh;
        a[8] += z.x * hh; a[9] += z.y * hh; a[10] += z.z * hh; a[11] += z.w * hh;
    }
    #pragma unroll
    for (int o = 16; o > 0; o >>= 1)
        #pragma unroll
        for (int i = 0; i < 12; ++i)
            a[i] += __shfl_xor_sync(0xFFFFFFFFu, a[i], o);
    a[0] += b0.x; a[1] += b0.y; a[2]  += b0.z; a[3]  += b0.w;
    a[4] += b1.x; a[5] += b1.y; a[6]  += b1.z; a[7]  += b1.w;
    a[8] += b2.x; a[9] += b2.y; a[10] += b2.z; a[11] += b2.w;
}

__global__ __launch_bounds__(NT, 1) void k_seq(
    float* __restrict__ out,                 // [T, 1024] = hidden|cell
    const float* __restrict__ U,
    const float* __restrict__ Uw,
    const float* __restrict__ Ua,
    const float* __restrict__ h0,
    const float* __restrict__ c0)
{
    extern __shared__ float sm[];
    unsigned* s_meta = (unsigned*)(sm + SM_META);
    float4* U4   = (float4*)(sm + SM_U);
    float4* UW4  = (float4*)(sm + SM_UW);
    float4* UA4  = (float4*)(sm + SM_UA);
    float4* RB4  = (float4*)(sm + SM_RB);
    float4* RAL4 = (float4*)(sm + SM_RAL);
    float4* RASH4= (float4*)(sm + SM_RASH);
    float4* CWO4 = (float4*)(sm + SM_CWO);
    float4* CPRV4= (float4*)(sm + SM_CPRV);
    float4* CSSH4= (float4*)(sm + SM_CSSH);

    const int c     = blockIdx.x;
    const int tid   = threadIdx.x;
    const int jbase = 4 * c;
    const int warp  = tid >> 5, lane = tid & 31;

    // ---- one-time: weight column slices + meta table ----
    for (int idx = tid; idx < 3 * 512; idx += NT) {
        int gate = idx >> 9, k = idx & 511;
        U4 [gate * 512 + k] = *(const float4*)(U  + (size_t)k * H3_ + gate * 512 + jbase);
        UW4[gate * 512 + k] = *(const float4*)(Uw + (size_t)k * H3_ + gate * 512 + jbase);
    }
    for (int k = tid; k < 512; k += NT)
        UA4[k] = *(const float4*)(Ua + (size_t)k * H_ + jbase);
    for (int i = tid; i < T_; i += NT) s_meta[i] = g_meta[i];
    __syncthreads();

    unsigned seq = 0;
    unsigned* myflag = &g_flag[c * 32];

    for (int t = 0; t < T_; ++t) {
        const unsigned meta = s_meta[t];
        const int nact = (int)(meta & 7u);
        const unsigned mN = (t + 1 < T_) ? s_meta[t + 1] : 0u;
        const int nactN = (int)(mN & 7u);

        int wT[4], dT[4], wN[4], dN[4];
        #pragma unroll
        for (int i = 0; i < 4; ++i) {
            unsigned f = meta >> (3 + 7 * i);
            wT[i] = (int)(f & 3u); dT[i] = (int)((f >> 2) & 31u);
            unsigned g = mN >> (3 + 7 * i);
            wN[i] = (int)(g & 3u); dN[i] = (int)((g >> 2) & 31u);
        }
        bool lateT = false;
        for (int i = 0; i < nact; ++i) lateT |= (dT[i] == 1);

        const float* rowHprev = t ? (out + (size_t)(t - 1) * 1024) : h0;
        const float* rowCprev = t ? (out + (size_t)(t - 1) * 1024 + 512) : c0;

        // ======== late phase: d==1 word gates (need h_{t-1}) ========
        if (lateT) {
            if (tid == 0) CPRV4[0] = *(const float4*)(rowCprev + jbase);
            // one fused task per d==1 word
            for (int wi = warp; wi < nact; wi += 8) {
                if (dT[wi] == 1) {
                    float a[12];
                    dot12(UW4, rowHprev,
                          g_GWx + ((size_t)t * WN_ + wT[wi]) * H3_ + jbase,
                          lane, a);
                    if (lane == 0) {
                        RASH4[wi * 3 + 0] = make_float4(a[0], a[1], a[2],  a[3]);
                        RASH4[wi * 3 + 1] = make_float4(a[4], a[5], a[6],  a[7]);
                        RASH4[wi * 3 + 2] = make_float4(a[8], a[9], a[10], a[11]);
                    }
                }
            }
            __syncthreads();
            ++seq;
            if (warp == 0) {
                if (lane >= 8 && lane < 8 + nact && dT[lane - 8] == 1) {
                    int wi = lane - 8;
                    float4 f4v = RASH4[wi * 3 + 0];
                    float4 i4v = RASH4[wi * 3 + 1];
                    float4 g4v = RASH4[wi * 3 + 2];
                    float4 cs  = CPRV4[0];
                    float4 cw;
                    cw.x = fsig(f4v.x) * cs.x + fsig(i4v.x) * ftan(g4v.x);
                    cw.y = fsig(f4v.y) * cs.y + fsig(i4v.y) * ftan(g4v.y);
                    cw.z = fsig(f4v.z) * cs.z + fsig(i4v.z) * ftan(g4v.z);
                    cw.w = fsig(f4v.w) * cs.w + fsig(i4v.w) * ftan(g4v.w);
                    *(float4*)(g_cwt + (size_t)t * 2048 + wi * 512 + jbase) = cw;
                    CWO4[(t & 1) * 4 + wi] = cw;
                }
                __syncwarp();
                if (lane == 0) st_rel(myflag, seq);
            }
            if (tid < GC) { while (ld_acq(&g_flag[tid * 32]) < seq) {} }
            __syncthreads();
        }

        // ======== main phase: flat task loop (one round typical) ========
        // [0,3): gate dots   [3,3+nact): alpha dots
        // [3+nact, 3+nact+nactN): fused shadow word dots for t+1 (d>=2)
        // [last]: c_prev micro-load
        const int base_sh = 3 + nact;
        const int ntasks  = base_sh + nactN + 1;
        for (int d = warp; d < ntasks; d += 8) {
            if (d < 3) {
                float4 r = dotg(U4 + d * 512, rowHprev,
                                g_XW + (size_t)t * H3_ + d * 512 + jbase, lane);
                if (lane == 0) RB4[d] = r;
            } else if (d < base_sh) {
                int wi = d - 3;
                float4 r = dotg(UA4, g_cwt + (size_t)t * 2048 + wi * 512,
                                g_XWa + (size_t)t * H_ + jbase, lane);
                if (lane == 0) RAL4[wi] = r;
            } else if (d < base_sh + nactN) {
                int wi = d - base_sh;
                if (dN[wi] >= 2) {
                    const float* row = out + (size_t)(t + 1 - dN[wi]) * 1024;
                    float4 cs = make_float4(0, 0, 0, 0);
                    if (lane == 1) cs = *(const float4*)(row + 512 + jbase);
                    float a[12];
                    dot12(UW4, row,
                          g_GWx + ((size_t)(t + 1) * WN_ + wN[wi]) * H3_ + jbase,
                          lane, a);
                    if (lane == 0) {
                        RASH4[wi * 3 + 0] = make_float4(a[0], a[1], a[2],  a[3]);
                        RASH4[wi * 3 + 1] = make_float4(a[4], a[5], a[6],  a[7]);
                        RASH4[wi * 3 + 2] = make_float4(a[8], a[9], a[10], a[11]);
                    }
                    if (lane == 1) CSSH4[wi] = cs;
                }
            } else {
                if (lane == 0) CPRV4[0] = *(const float4*)(rowCprev + jbase);
            }
        }
        __syncthreads();

        // ======== finalize (warp 0): combine on lanes 0-3, shadow cw on 8-11 ====
        ++seq;
        if (warp == 0) {
            if (lane < 4) {
                // per-column combine (parallel over 4 output columns)
                int jl = lane;
                float gi = sm[SM_RB + 0 + jl];
                float go = sm[SM_RB + 4 + jl];
                float gg = sm[SM_RB + 8 + jl];
                float ig = fsig(gi), og = fsig(go), gt = ftan(gg);
                float c1;
                if (nact) {
                    float den = __expf(ig), num = den * gt;
                    for (int wi = 0; wi < nact; ++wi) {
                        float al = sm[SM_RAL + wi * 4 + jl];
                        float cw = sm[SM_CWO + (t & 1) * 16 + wi * 4 + jl];
                        float e  = __expf(fsig(al));
                        den += e; num += e * cw;
                    }
                    c1 = num / den;
                } else {
                    float cp = sm[SM_CPRV + jl];
                    c1 = (1.0f - ig) * cp + ig * gt;
                }
                float h1 = og * ftan(c1);
                out[(size_t)t * 1024 + jbase + jl]       = h1;
                out[(size_t)t * 1024 + 512 + jbase + jl] = c1;
            } else if (lane >= 8 && lane < 8 + nactN && dN[lane - 8] >= 2) {
                // finalize shadow c_w(t+1)
                int wi = lane - 8;
                float4 f4v = RASH4[wi * 3 + 0];
                float4 i4v = RASH4[wi * 3 + 1];
                float4 g4v = RASH4[wi * 3 + 2];
                float4 cs  = CSSH4[wi];
                float4 cw;
                cw.x = fsig(f4v.x) * cs.x + fsig(i4v.x) * ftan(g4v.x);
                cw.y = fsig(f4v.y) * cs.y + fsig(i4v.y) * ftan(g4v.y);
                cw.z = fsig(f4v.z) * cs.z + fsig(i4v.z) * ftan(g4v.z);
                cw.w = fsig(f4v.w) * cs.w + fsig(i4v.w) * ftan(g4v.w);
                *(float4*)(g_cwt + (size_t)(t + 1) * 2048 + wi * 512 + jbase) = cw;
                CWO4[((t + 1) & 1) * 4 + wi] = cw;
            }
            __syncwarp();
            if (lane == 0) st_rel(myflag, seq);
        }
        // ======== barrier ========
        if (tid < GC) { while (ld_acq(&g_flag[tid * 32]) < seq) {} }
        __syncthreads();
    }
}

// ---------------- launch (4 kernels) ----------------
extern "C" void kernel_launch(void* const* d_in, const int* in_sizes, int n_in,
                              void* d_out, int out_size) {
    const float* x        = (const float*)d_in[0];
    const int*   word_ids = (const int*)  d_in[1];
    const int*   wstarts  = (const int*)  d_in[2];
    const void*  wmask    = (const void*) d_in[3];
    const float* h0       = (const float*)d_in[4];
    const float* c0       = (const float*)d_in[5];
    const float* emb      = (const float*)d_in[6];
    const float* W        = (const float*)d_in[7];
    const float* U        = (const float*)d_in[8];
    const float* b        = (const float*)d_in[9];
    const float* Wa       = (const float*)d_in[10];
    const float* Ua       = (const float*)d_in[11];
    const float* ba       = (const float*)d_in[12];
    const float* Ww       = (const float*)d_in[13];
    const float* Uw       = (const float*)d_in[14];
    const float* bw       = (const float*)d_in[15];
    float* out = (float*)d_out;

    k_prep<<<1, 1024>>>((const unsigned*)wmask, wmask, wstarts);

    dim3 gx(32, T_ / 128);
    k_gemm<<<gx, 256>>>(x, nullptr, W, b, Wa, ba, T_, D_, 3);
    dim3 gw(H3_ / 64, (T_ * WN_) / 128);
    k_gemm<<<gw, 256>>>(emb, word_ids, Ww, bw, nullptr, nullptr, T_ * WN_, 256, 2);

    static_assert(SMEM_BYTES < 220 * 1024, "smem");
    cudaFuncSetAttribute(k_seq, cudaFuncAttributeMaxDynamicSharedMemorySize,
                         SMEM_BYTES);
    k_seq<<<GC, NT, SMEM_BYTES>>>(out, U, Uw, Ua, h0, c0);
}